// round 17
// baseline (speedup 1.0000x reference)
#include <cuda_runtime.h>
#include <cuda_fp16.h>
#include <math.h>
#include <stdint.h>

// Problem constants
#define TSEQ    2048
#define BATCH   2
#define DMODEL  1024
#define NHEAD   16
#define HEADDIM 64
#define FFDIM   4096
#define NLAYER  4
#define ROWS    (BATCH * TSEQ)          // 4096
#define QKVDIM  (3 * DMODEL)            // 3072
#define QKPITCH (2 * DMODEL)            // 2048

// -------------------- scratch (allocation-free) --------------------
__device__ float g_x  [ROWS * DMODEL];          // residual stream fp32
__device__ __half g_xn [ROWS * DMODEL];
__device__ __half g_att[ROWS * DMODEL];
__device__ __half g_h  [ROWS * FFDIM];
__device__ __half g_qk_h[ROWS * QKPITCH];
__device__ __half g_qk_l[ROWS * QKPITCH];
__device__ __half g_vt_h[BATCH * NHEAD * HEADDIM * TSEQ];
__device__ __half g_vt_l[BATCH * NHEAD * HEADDIM * TSEQ];
__device__ __half g_wi[NLAYER * QKVDIM * DMODEL];
__device__ __half g_wo[NLAYER * DMODEL * DMODEL];
__device__ __half g_w1[NLAYER * FFDIM * DMODEL];
__device__ __half g_w2[NLAYER * DMODEL * FFDIM];

// -------------------- helpers --------------------
__device__ __forceinline__ void cp_async16(uint32_t smem, const void* g) {
    asm volatile("cp.async.cg.shared.global [%0], [%1], 16;\n" :: "r"(smem), "l"(g));
}
__device__ __forceinline__ void cp_commit() {
    asm volatile("cp.async.commit_group;\n" ::: "memory");
}
__device__ __forceinline__ void cp_wait0() {
    asm volatile("cp.async.wait_group 0;\n" ::: "memory");
}
__device__ __forceinline__ uint32_t smem_u32(const void* p) {
    return (uint32_t)__cvta_generic_to_shared(p);
}
__device__ __forceinline__ void split2h(float v, __half& h, __half& l) {
    h = __float2half_rn(v);
    l = __float2half_rn(v - __half2float(h));
}
__device__ __forceinline__ uint32_t packh(float a, float b) {
    __half2 t = __floats2half2_rn(a, b);
    return *(uint32_t*)&t;
}
__device__ __forceinline__ void splitpackh(float a, float b, uint32_t& hi, uint32_t& lo) {
    __half ha, la, hb, lb;
    split2h(a, ha, la); split2h(b, hb, lb);
    __half2 ph; ph.x = ha; ph.y = hb;
    __half2 pl; pl.x = la; pl.y = lb;
    hi = *(uint32_t*)&ph; lo = *(uint32_t*)&pl;
}
__device__ __forceinline__ void mma_f16(float* d, const uint32_t* a, uint32_t b0, uint32_t b1) {
    asm volatile(
        "mma.sync.aligned.m16n8k16.row.col.f32.f16.f16.f32 "
        "{%0,%1,%2,%3}, {%4,%5,%6,%7}, {%8,%9}, {%0,%1,%2,%3};\n"
        : "+f"(d[0]), "+f"(d[1]), "+f"(d[2]), "+f"(d[3])
        : "r"(a[0]), "r"(a[1]), "r"(a[2]), "r"(a[3]),
          "r"(b0), "r"(b1));
}

// -------------------- copy --------------------
__global__ void copy_kernel(const float4* __restrict__ in, float4* __restrict__ out, int n4) {
    int i = blockIdx.x * blockDim.x + threadIdx.x;
    if (i < n4) out[i] = in[i];
}

// -------------------- merged weight convert (fp32 -> fp16 single plane) --------------------
#define S0 (NLAYER * QKVDIM * DMODEL / 4)
#define S1 (NLAYER * DMODEL * DMODEL / 4)
#define S2 (NLAYER * FFDIM * DMODEL / 4)
#define S3 (NLAYER * DMODEL * FFDIM / 4)
#define SPLIT_TOTAL (S0 + S1 + S2 + S3)

__global__ void convert_all_kernel(
    const float4* __restrict__ in0, const float4* __restrict__ in1,
    const float4* __restrict__ in2, const float4* __restrict__ in3,
    uint32_t* __restrict__ h0, uint32_t* __restrict__ h1,
    uint32_t* __restrict__ h2, uint32_t* __restrict__ h3)
{
    int i = blockIdx.x * blockDim.x + threadIdx.x;
    if (i >= SPLIT_TOTAL) return;
    const float4* in; uint32_t* hi;
    int j = i;
    if (j < S0)                 { in = in0; hi = h0; }
    else if ((j -= S0) < S1)    { in = in1; hi = h1; }
    else if ((j -= S1) < S2)    { in = in2; hi = h2; }
    else                        { j -= S2; in = in3; hi = h3; }
    float4 v = in[j];
    hi[j * 2 + 0] = packh(v.x, v.y);
    hi[j * 2 + 1] = packh(v.z, v.w);
}

// -------------------- layernorm (fp32 out — final) --------------------
__global__ void __launch_bounds__(256) ln_kernel(
    const float* __restrict__ in, const float* __restrict__ w,
    const float* __restrict__ b, float* __restrict__ out)
{
    int row = blockIdx.x;
    int tid = threadIdx.x;
    const float4* ip = (const float4*)(in + (size_t)row * DMODEL);
    float4 v = ip[tid];
    float s  = v.x + v.y + v.z + v.w;
    float sq = v.x * v.x + v.y * v.y + v.z * v.z + v.w * v.w;
    #pragma unroll
    for (int o = 16; o > 0; o >>= 1) {
        s  += __shfl_xor_sync(0xffffffffu, s,  o);
        sq += __shfl_xor_sync(0xffffffffu, sq, o);
    }
    __shared__ float reds[8], redq[8];
    int lane = tid & 31, wid = tid >> 5;
    if (lane == 0) { reds[wid] = s; redq[wid] = sq; }
    __syncthreads();
    float ts = 0.f, tq = 0.f;
    #pragma unroll
    for (int i = 0; i < 8; i++) { ts += reds[i]; tq += redq[i]; }
    float mean = ts * (1.0f / DMODEL);
    float var  = tq * (1.0f / DMODEL) - mean * mean;
    float rstd = rsqrtf(var + 1e-5f);
    float4 wv = ((const float4*)w)[tid];
    float4 bv = ((const float4*)b)[tid];
    float4 r;
    r.x = (v.x - mean) * rstd * wv.x + bv.x;
    r.y = (v.y - mean) * rstd * wv.y + bv.y;
    r.z = (v.z - mean) * rstd * wv.z + bv.z;
    r.w = (v.w - mean) * rstd * wv.w + bv.w;
    ((float4*)(out + (size_t)row * DMODEL))[tid] = r;
}

// -------------------- layernorm (fp16 out) --------------------
__global__ void __launch_bounds__(256) ln_half_kernel(
    const float* __restrict__ in, const float* __restrict__ w,
    const float* __restrict__ b, __half* __restrict__ oh)
{
    int row = blockIdx.x;
    int tid = threadIdx.x;
    const float4* ip = (const float4*)(in + (size_t)row * DMODEL);
    float4 v = ip[tid];
    float s  = v.x + v.y + v.z + v.w;
    float sq = v.x * v.x + v.y * v.y + v.z * v.z + v.w * v.w;
    #pragma unroll
    for (int o = 16; o > 0; o >>= 1) {
        s  += __shfl_xor_sync(0xffffffffu, s,  o);
        sq += __shfl_xor_sync(0xffffffffu, sq, o);
    }
    __shared__ float reds[8], redq[8];
    int lane = tid & 31, wid = tid >> 5;
    if (lane == 0) { reds[wid] = s; redq[wid] = sq; }
    __syncthreads();
    float ts = 0.f, tq = 0.f;
    #pragma unroll
    for (int i = 0; i < 8; i++) { ts += reds[i]; tq += redq[i]; }
    float mean = ts * (1.0f / DMODEL);
    float var  = tq * (1.0f / DMODEL) - mean * mean;
    float rstd = rsqrtf(var + 1e-5f);
    float4 wv = ((const float4*)w)[tid];
    float4 bv = ((const float4*)b)[tid];
    float r0 = (v.x - mean) * rstd * wv.x + bv.x;
    float r1 = (v.y - mean) * rstd * wv.y + bv.y;
    float r2 = (v.z - mean) * rstd * wv.z + bv.z;
    float r3 = (v.w - mean) * rstd * wv.w + bv.w;
    size_t base = (size_t)row * DMODEL + tid * 4;
    *(uint32_t*)(oh + base)     = packh(r0, r1);
    *(uint32_t*)(oh + base + 2) = packh(r2, r3);
}

// -------------------- pure-fp16 tensor-core GEMM (64x64 warp tile) --------------------
// C[M,N] = A[M,K] @ W[N,K]^T + bias; A,W fp16 single planes (K-major).
// Block 256(M) x 128(N), BK=32, 8 warps (4M x 2N), warp tile 64x64.
// LDS:mma = 1:1 per ks (16 A + 16 B loads feed 32 mma). 1 CTA/SM (regs ~175).
// EPI: 1 = bias+GELU -> fp16 ; 2 = bias+residual -> fp32 ; 3 = QKV epilogue
#define GPITCH 40
#define A_ELE (256 * GPITCH)
#define W_ELE (128 * GPITCH)
#define STG_ELE (A_ELE + W_ELE)               // 15360 halfs
#define GEMM_SMEM (2 * STG_ELE * 2)           // 61440 bytes

template <int EPI>
__global__ void __launch_bounds__(256, 1) gemm_f16(
    const __half* __restrict__ A, const __half* __restrict__ W,
    const float* __restrict__ bias, const float* __restrict__ res,
    float* __restrict__ Cf, __half* __restrict__ Ch, __half* __restrict__ Kl,
    __half* __restrict__ Vth, __half* __restrict__ Vtl,
    int M, int N, int K)
{
    extern __shared__ __half smem[];
    uint32_t sbase = smem_u32(smem);

    int tid  = threadIdx.x;
    int lane = tid & 31;
    int wid  = tid >> 5;
    int warpM = (wid >> 1) * 64;      // 0,64,128,192
    int warpN = (wid & 1) * 64;       // 0,64
    int m0 = blockIdx.y * 256;
    int n0 = blockIdx.x * 128;

    int gr = lane >> 2;
    int gc = lane & 3;

    float acc[4][8][4];
    #pragma unroll
    for (int i = 0; i < 4; i++)
        #pragma unroll
        for (int j = 0; j < 8; j++)
            #pragma unroll
            for (int c = 0; c < 4; c++) acc[i][j][c] = 0.f;

    int KT = K >> 5;

    auto load_chunk = [&](int kt) {
        uint32_t sb = sbase + (uint32_t)(kt & 1) * STG_ELE * 2;
        int k0 = kt << 5;
        #pragma unroll
        for (int i = 0; i < 4; i++) {
            int idx = tid + i * 256;          // 0..1023
            int row = idx >> 2;               // 0..255
            int k16 = idx & 3;
            uint32_t so = (uint32_t)(row * 80 + k16 * 16);
            size_t ga = (size_t)(m0 + row) * K + k0 + k16 * 8;
            cp_async16(sb + so, A + ga);
        }
        #pragma unroll
        for (int i = 0; i < 2; i++) {
            int idx = tid + i * 256;          // 0..511
            int row = idx >> 2;               // 0..127
            int k16 = idx & 3;
            uint32_t so = (uint32_t)(row * 80 + k16 * 16);
            size_t gw = (size_t)(n0 + row) * K + k0 + k16 * 8;
            cp_async16(sb + A_ELE * 2 + so, W + gw);
        }
        cp_commit();
    };

    load_chunk(0);

    for (int kt = 0; kt < KT; kt++) {
        cp_wait0();
        __syncthreads();
        if (kt + 1 < KT) load_chunk(kt + 1);

        const char* stg = (const char*)smem + (size_t)(kt & 1) * STG_ELE * 2;
        const char* sA = stg;
        const char* sW = stg + A_ELE * 2;

        #pragma unroll
        for (int ks = 0; ks < 2; ks++) {
            int kby = ks * 32 + gc * 4;
            uint32_t ah[4][4];
            #pragma unroll
            for (int mt = 0; mt < 4; mt++) {
                int r = warpM + mt * 16 + gr;
                const char* p0 = sA + r * 80 + kby;
                const char* p1 = sA + (r + 8) * 80 + kby;
                ah[mt][0] = *(const uint32_t*)p0;
                ah[mt][1] = *(const uint32_t*)p1;
                ah[mt][2] = *(const uint32_t*)(p0 + 16);
                ah[mt][3] = *(const uint32_t*)(p1 + 16);
            }
            #pragma unroll
            for (int np = 0; np < 4; np++) {
                int c0 = warpN + (2 * np) * 8 + gr;
                int c1 = warpN + (2 * np + 1) * 8 + gr;
                uint32_t b00, b01, b10, b11;
                {
                    const char* p = sW + c0 * 80 + kby;
                    b00 = *(const uint32_t*)p; b01 = *(const uint32_t*)(p + 16);
                    const char* p2 = sW + c1 * 80 + kby;
                    b10 = *(const uint32_t*)p2; b11 = *(const uint32_t*)(p2 + 16);
                }
                #pragma unroll
                for (int mt = 0; mt < 4; mt++) {
                    mma_f16(acc[mt][2 * np],     ah[mt], b00, b01);
                    mma_f16(acc[mt][2 * np + 1], ah[mt], b10, b11);
                }
            }
        }
        __syncthreads();
    }

    // ---- epilogue ----
    #pragma unroll
    for (int mt = 0; mt < 4; mt++) {
        int r0 = m0 + warpM + mt * 16 + gr;
        #pragma unroll
        for (int nt = 0; nt < 8; nt++) {
            int col = n0 + warpN + nt * 8 + 2 * gc;
            float b0 = bias[col], b1 = bias[col + 1];
            #pragma unroll
            for (int half_ = 0; half_ < 2; half_++) {
                int row = r0 + half_ * 8;
                float v0 = acc[mt][nt][2 * half_ + 0] + b0;
                float v1 = acc[mt][nt][2 * half_ + 1] + b1;
                if (EPI == 1) {
                    v0 = 0.5f * v0 * (1.0f + erff(v0 * 0.70710678118654752f));
                    v1 = 0.5f * v1 * (1.0f + erff(v1 * 0.70710678118654752f));
                    *(uint32_t*)(Ch + (size_t)row * N + col) = packh(v0, v1);
                } else if (EPI == 2) {
                    const float2 rv = *(const float2*)(res + (size_t)row * N + col);
                    v0 += rv.x; v1 += rv.y;
                    float2 o2; o2.x = v0; o2.y = v1;
                    *(float2*)(Cf + (size_t)row * N + col) = o2;
                } else {   // EPI == 3: QKV epilogue
                    if (col >= 2 * DMODEL) {
                        int c  = col - 2 * DMODEL;
                        int hh = c >> 6, d = c & 63;
                        int bb = row >> 11, t = row & (TSEQ - 1);
                        size_t vi = ((size_t)((bb * NHEAD + hh) * HEADDIM + d)) * TSEQ + t;
                        __half h0, l0v, h1, l1v;
                        split2h(v0, h0, l0v); split2h(v1, h1, l1v);
                        Vth[vi] = h0;        Vtl[vi] = l0v;
                        Vth[vi + TSEQ] = h1; Vtl[vi + TSEQ] = l1v;
                    } else if (col >= DMODEL) {
                        uint32_t ph, pl;
                        splitpackh(v0, v1, ph, pl);
                        size_t base = (size_t)row * QKPITCH + col;
                        *(uint32_t*)(Ch + base) = ph;
                        *(uint32_t*)(Kl + base) = pl;
                    } else {
                        *(uint32_t*)(Ch + (size_t)row * QKPITCH + col) = packh(v0, v1);
                    }
                }
            }
        }
    }
}

// -------------------- mma flash attention (fp16 2-term, causal + ALiBi) --------------------
#define KV_PITCH_B 144
#define KV_TILE_B (64 * KV_PITCH_B)
#define ATT_STAGE (4 * KV_TILE_B)
#define ATT_SMEM  (2 * ATT_STAGE)              // 73728

__global__ void __launch_bounds__(128) attn_mma_kernel(
    const __half* __restrict__ qkh, const __half* __restrict__ qkl,
    const __half* __restrict__ vth, const __half* __restrict__ vtl,
    __half* __restrict__ oh)
{
    extern __shared__ char asmem[];
    uint32_t sbase = smem_u32(asmem);

    int b = blockIdx.z, h = blockIdx.y;
    int qt = gridDim.x - 1 - blockIdx.x;
    int tid = threadIdx.x, lane = tid & 31, w = tid >> 5;
    int gr = lane >> 2, gc = lane & 3;

    int hcol = h * HEADDIM;
    int qrow0 = b * TSEQ + qt * 64;

    uint32_t qh[4][4];
    {
        const __half* qp = qkh + (size_t)(qrow0 + w * 16) * QKPITCH + hcol;
        #pragma unroll
        for (int kc = 0; kc < 4; kc++) {
            int c = kc * 16 + 2 * gc;
            qh[kc][0] = *(const uint32_t*)(qp + (size_t)gr * QKPITCH + c);
            qh[kc][1] = *(const uint32_t*)(qp + (size_t)(gr + 8) * QKPITCH + c);
            qh[kc][2] = *(const uint32_t*)(qp + (size_t)gr * QKPITCH + c + 8);
            qh[kc][3] = *(const uint32_t*)(qp + (size_t)(gr + 8) * QKPITCH + c + 8);
        }
    }

    auto load_kv = [&](int kt, int s) {
        uint32_t sb = sbase + (uint32_t)s * ATT_STAGE;
        const __half* Kh = qkh + (size_t)(b * TSEQ + kt * 64) * QKPITCH + DMODEL + hcol;
        const __half* Kl = qkl + (size_t)(b * TSEQ + kt * 64) * QKPITCH + DMODEL + hcol;
        size_t vbase = (size_t)((b * NHEAD + h) * HEADDIM) * TSEQ + kt * 64;
        #pragma unroll
        for (int i = 0; i < 4; i++) {
            int idx = tid + i * 128;
            int r   = idx >> 3;
            int c16 = idx & 7;
            uint32_t so = (uint32_t)(r * KV_PITCH_B + c16 * 16);
            cp_async16(sb + so,                  Kh  + (size_t)r * QKPITCH + c16 * 8);
            cp_async16(sb + KV_TILE_B + so,      Kl  + (size_t)r * QKPITCH + c16 * 8);
            cp_async16(sb + 2 * KV_TILE_B + so,  vth + vbase + (size_t)r * TSEQ + c16 * 8);
            cp_async16(sb + 3 * KV_TILE_B + so,  vtl + vbase + (size_t)r * TSEQ + c16 * 8);
        }
        cp_commit();
    };

    float m0 = -INFINITY, m1 = -INFINITY, l0 = 0.f, l1 = 0.f;
    float acc_o[8][4];
    #pragma unroll
    for (int nt = 0; nt < 8; nt++)
        #pragma unroll
        for (int j = 0; j < 4; j++) acc_o[nt][j] = 0.f;

    float slope = exp2f(-0.5f * (float)(h + 1));
    int qpos0 = qt * 64 + w * 16 + gr;

    load_kv(0, 0);

    for (int kt = 0; kt <= qt; kt++) {
        int s = kt & 1;
        cp_wait0();
        __syncthreads();
        if (kt < qt) load_kv(kt + 1, s ^ 1);

        const char* Ksh = asmem + (size_t)s * ATT_STAGE;
        const char* Ksl = Ksh + KV_TILE_B;
        const char* Vsh = Ksh + 2 * KV_TILE_B;
        const char* Vsl = Ksh + 3 * KV_TILE_B;

        // ---- S = Q_h (K_h + K_l) ----
        float sacc[8][4];
        #pragma unroll
        for (int nt = 0; nt < 8; nt++)
            #pragma unroll
            for (int j = 0; j < 4; j++) sacc[nt][j] = 0.f;

        #pragma unroll
        for (int kc = 0; kc < 4; kc++) {
            int kby = kc * 32 + gc * 4;
            #pragma unroll
            for (int np = 0; np < 4; np++) {
                int c0 = (2 * np) * 8 + gr;
                int c1 = (2 * np + 1) * 8 + gr;
                uint32_t b0h0, b0h1, b0l0, b0l1, b1h0, b1h1, b1l0, b1l1;
                {
                    const char* p = Ksh + c0 * KV_PITCH_B + kby;
                    b0h0 = *(const uint32_t*)p; b0h1 = *(const uint32_t*)(p + 16);
                    const char* q = Ksl + c0 * KV_PITCH_B + kby;
                    b0l0 = *(const uint32_t*)q; b0l1 = *(const uint32_t*)(q + 16);
                    const char* p2 = Ksh + c1 * KV_PITCH_B + kby;
                    b1h0 = *(const uint32_t*)p2; b1h1 = *(const uint32_t*)(p2 + 16);
                    const char* q2 = Ksl + c1 * KV_PITCH_B + kby;
                    b1l0 = *(const uint32_t*)q2; b1l1 = *(const uint32_t*)(q2 + 16);
                }
                float* s0 = sacc[2 * np];
                float* s1 = sacc[2 * np + 1];
                mma_f16(s0, qh[kc], b0h0, b0h1);
                mma_f16(s1, qh[kc], b1h0, b1h1);
                mma_f16(s0, qh[kc], b0l0, b0l1);
                mma_f16(s1, qh[kc], b1l0, b1l1);
            }
        }

        // ---- mask + ALiBi + online softmax ----
        int kbase = kt * 64;
        float tmax0 = -INFINITY, tmax1 = -INFINITY;
        #pragma unroll
        for (int nt = 0; nt < 8; nt++) {
            #pragma unroll
            for (int j = 0; j < 4; j++) {
                int kp = kbase + nt * 8 + 2 * gc + (j & 1);
                int qp = qpos0 + ((j >> 1) << 3);
                float sv = (kp <= qp)
                    ? sacc[nt][j] * 0.125f + slope * (float)(kp - qp)
                    : -INFINITY;
                sacc[nt][j] = sv;
                if (j < 2) tmax0 = fmaxf(tmax0, sv);
                else       tmax1 = fmaxf(tmax1, sv);
            }
        }
        tmax0 = fmaxf(tmax0, __shfl_xor_sync(0xffffffffu, tmax0, 1));
        tmax0 = fmaxf(tmax0, __shfl_xor_sync(0xffffffffu, tmax0, 2));
        tmax1 = fmaxf(tmax1, __shfl_xor_sync(0xffffffffu, tmax1, 1));
        tmax1 = fmaxf(tmax1, __shfl_xor_sync(0xffffffffu, tmax1, 2));

        float nm0 = fmaxf(m0, tmax0);
        float nm1 = fmaxf(m1, tmax1);
        float corr0 = __expf(m0 - nm0);
        float corr1 = __expf(m1 - nm1);
        m0 = nm0; m1 = nm1;
        l0 *= corr0; l1 *= corr1;
        #pragma unroll
        for (int nt = 0; nt < 8; nt++) {
            acc_o[nt][0] *= corr0; acc_o[nt][1] *= corr0;
            acc_o[nt][2] *= corr1; acc_o[nt][3] *= corr1;
        }

        float ts0 = 0.f, ts1 = 0.f;
        #pragma unroll
        for (int nt = 0; nt < 8; nt++) {
            #pragma unroll
            for (int j = 0; j < 4; j++) {
                float p = __expf(sacc[nt][j] - ((j < 2) ? m0 : m1));
                sacc[nt][j] = p;
                if (j < 2) ts0 += p; else ts1 += p;
            }
        }
        ts0 += __shfl_xor_sync(0xffffffffu, ts0, 1);
        ts0 += __shfl_xor_sync(0xffffffffu, ts0, 2);
        ts1 += __shfl_xor_sync(0xffffffffu, ts1, 1);
        ts1 += __shfl_xor_sync(0xffffffffu, ts1, 2);
        l0 += ts0; l1 += ts1;

        // ---- O += P_h (V_h + V_l) ----
        #pragma unroll
        for (int kc = 0; kc < 4; kc++) {
            uint32_t ph[4];
            ph[0] = packh(sacc[2 * kc][0],     sacc[2 * kc][1]);
            ph[1] = packh(sacc[2 * kc][2],     sacc[2 * kc][3]);
            ph[2] = packh(sacc[2 * kc + 1][0], sacc[2 * kc + 1][1]);
            ph[3] = packh(sacc[2 * kc + 1][2], sacc[2 * kc + 1][3]);
            int kby = kc * 32 + gc * 4;
            #pragma unroll
            for (int np = 0; np < 4; np++) {
                int c0 = (2 * np) * 8 + gr;
                int c1 = (2 * np + 1) * 8 + gr;
                uint32_t b0h0, b0h1, b0l0, b0l1, b1h0, b1h1, b1l0, b1l1;
                {
                    const char* p = Vsh + c0 * KV_PITCH_B + kby;
                    b0h0 = *(const uint32_t*)p; b0h1 = *(const uint32_t*)(p + 16);
                    const char* q = Vsl + c0 * KV_PITCH_B + kby;
                    b0l0 = *(const uint32_t*)q; b0l1 = *(const uint32_t*)(q + 16);
                    const char* p2 = Vsh + c1 * KV_PITCH_B + kby;
                    b1h0 = *(const uint32_t*)p2; b1h1 = *(const uint32_t*)(p2 + 16);
                    const char* q2 = Vsl + c1 * KV_PITCH_B + kby;
                    b1l0 = *(const uint32_t*)q2; b1l1 = *(const uint32_t*)(q2 + 16);
                }
                float* o0 = acc_o[2 * np];
                float* o1 = acc_o[2 * np + 1];
                mma_f16(o0, ph, b0h0, b0h1);
                mma_f16(o1, ph, b1h0, b1h1);
                mma_f16(o0, ph, b0l0, b0l1);
                mma_f16(o1, ph, b1l0, b1l1);
            }
        }
    }

    // ---- epilogue ----
    float inv0 = 1.0f / l0, inv1 = 1.0f / l1;
    int r0 = qrow0 + w * 16 + gr;
    #pragma unroll
    for (int nt = 0; nt < 8; nt++) {
        int col = hcol + nt * 8 + 2 * gc;
        size_t b0 = (size_t)r0 * DMODEL + col;
        size_t b1 = (size_t)(r0 + 8) * DMODEL + col;
        *(uint32_t*)(oh + b0) = packh(acc_o[nt][0] * inv0, acc_o[nt][1] * inv0);
        *(uint32_t*)(oh + b1) = packh(acc_o[nt][2] * inv1, acc_o[nt][3] * inv1);
    }
}

// -------------------- launch --------------------
extern "C" void kernel_launch(void* const* d_in, const int* in_sizes, int n_in,
                              void* d_out, int out_size)
{
    const float* x        = (const float*)d_in[0];
    const float* in_w     = (const float*)d_in[1];
    const float* in_b     = (const float*)d_in[2];
    const float* out_w    = (const float*)d_in[3];
    const float* out_b    = (const float*)d_in[4];
    const float* f1_w     = (const float*)d_in[5];
    const float* f1_b     = (const float*)d_in[6];
    const float* f2_w     = (const float*)d_in[7];
    const float* f2_b     = (const float*)d_in[8];
    const float* ln1_w    = (const float*)d_in[9];
    const float* ln1_b    = (const float*)d_in[10];
    const float* ln2_w    = (const float*)d_in[11];
    const float* ln2_b    = (const float*)d_in[12];
    const float* final_w  = (const float*)d_in[13];
    const float* final_b  = (const float*)d_in[14];

    float *x_;
    __half *xn, *att, *hbuf, *qkh, *qkl, *vth, *vtl;
    __half *wi, *wo, *w1, *w2;
    cudaGetSymbolAddress((void**)&x_,   g_x);
    cudaGetSymbolAddress((void**)&xn,   g_xn);
    cudaGetSymbolAddress((void**)&att,  g_att);
    cudaGetSymbolAddress((void**)&hbuf, g_h);
    cudaGetSymbolAddress((void**)&qkh,  g_qk_h);
    cudaGetSymbolAddress((void**)&qkl,  g_qk_l);
    cudaGetSymbolAddress((void**)&vth,  g_vt_h);
    cudaGetSymbolAddress((void**)&vtl,  g_vt_l);
    cudaGetSymbolAddress((void**)&wi,   g_wi);
    cudaGetSymbolAddress((void**)&wo,   g_wo);
    cudaGetSymbolAddress((void**)&w1,   g_w1);
    cudaGetSymbolAddress((void**)&w2,   g_w2);

    cudaFuncSetAttribute(gemm_f16<1>, cudaFuncAttributeMaxDynamicSharedMemorySize, GEMM_SMEM);
    cudaFuncSetAttribute(gemm_f16<2>, cudaFuncAttributeMaxDynamicSharedMemorySize, GEMM_SMEM);
    cudaFuncSetAttribute(gemm_f16<3>, cudaFuncAttributeMaxDynamicSharedMemorySize, GEMM_SMEM);
    cudaFuncSetAttribute(attn_mma_kernel, cudaFuncAttributeMaxDynamicSharedMemorySize, ATT_SMEM);

    convert_all_kernel<<<(SPLIT_TOTAL + 255) / 256, 256>>>(
        (const float4*)in_w, (const float4*)out_w, (const float4*)f1_w, (const float4*)f2_w,
        (uint32_t*)wi, (uint32_t*)wo, (uint32_t*)w1, (uint32_t*)w2);

    {
        int n4 = ROWS * DMODEL / 4;
        copy_kernel<<<(n4 + 255) / 256, 256>>>((const float4*)x, (float4*)x_, n4);
    }

    dim3 blk256(256);
    for (int i = 0; i < NLAYER; i++) {
        __half* iw  = wi + (size_t)i * QKVDIM * DMODEL;
        __half* ow  = wo + (size_t)i * DMODEL * DMODEL;
        __half* f1p = w1 + (size_t)i * FFDIM * DMODEL;
        __half* f2p = w2 + (size_t)i * DMODEL * FFDIM;
        const float* ib = in_b  + (size_t)i * QKVDIM;
        const float* ob = out_b + (size_t)i * DMODEL;
        const float* b1 = f1_b  + (size_t)i * FFDIM;
        const float* b2 = f2_b  + (size_t)i * DMODEL;

        ln_half_kernel<<<ROWS, blk256>>>(x_, ln1_w + i * DMODEL, ln1_b + i * DMODEL, xn);
        gemm_f16<3><<<dim3(QKVDIM / 128, ROWS / 256), blk256, GEMM_SMEM>>>(
            xn, iw, ib, nullptr, nullptr, qkh, qkl, vth, vtl,
            ROWS, QKVDIM, DMODEL);
        attn_mma_kernel<<<dim3(TSEQ / 64, NHEAD, BATCH), 128, ATT_SMEM>>>(
            qkh, qkl, vth, vtl, att);
        gemm_f16<2><<<dim3(DMODEL / 128, ROWS / 256), blk256, GEMM_SMEM>>>(
            att, ow, ob, x_, x_, nullptr, nullptr, nullptr, nullptr,
            ROWS, DMODEL, DMODEL);
        ln_half_kernel<<<ROWS, blk256>>>(x_, ln2_w + i * DMODEL, ln2_b + i * DMODEL, xn);
        gemm_f16<1><<<dim3(FFDIM / 128, ROWS / 256), blk256, GEMM_SMEM>>>(
            xn, f1p, b1, nullptr, nullptr, hbuf, nullptr, nullptr, nullptr,
            ROWS, FFDIM, DMODEL);
        gemm_f16<2><<<dim3(DMODEL / 128, ROWS / 256), blk256, GEMM_SMEM>>>(
            hbuf, f2p, b2, x_, x_, nullptr, nullptr, nullptr, nullptr,
            ROWS, DMODEL, FFDIM);
    }
    ln_kernel<<<ROWS, blk256>>>(x_, final_w, final_b, (float*)d_out);
}